// round 12
// baseline (speedup 1.0000x reference)
#include <cuda_runtime.h>
#include <cuda_bf16.h>
#include <math.h>

// GRU: B=256, T=512, H=512, L=2, O=2.
// Persistent kernel; bf16 hi/lo split GEMM on mma.sync.m16n8k16 (fp32 accum).
// tcgen05 unavailable (harness ptxas targets sm_103 without 'a').
//
// 288 fixed 128x32 output tiles, one per CTA, 2 CTAs/SM (occupancy doubled vs
// the 128x64 version to hide act/barrier/staging latency). Each CTA pins its
// 32x512 weight slice in smem (bf16 hi+lo); A (=h hi/lo) streams through a
// 2-stage cp.async pipeline. Per step: tile wave; grid barrier; fused
// activations; grid barrier. Final: out = h1 @ fc_w^T + fc_b.

#define BT 256
#define TT 512
#define HH 512
#define NG 1536
#define NCTA 288
#define NTHR 256

#define WST 520                        // W smem row stride (bf16 elems)
#define AST 40                         // A smem row stride (bf16 elems)
#define SMEM_W (32 * WST * 2)          // 33,280 B per W array (hi or lo)
#define ABUF   (128 * AST * 2)         // 10,240 B per (stage, hi/lo)
#define W_OFF  0
#define A_OFF  (2 * SMEM_W)            // 66,560
#define NSTAGE 2
#define SMEM_BYTES (A_OFF + NSTAGE * 2 * ABUF)   // 107,520 B  (x2 CTAs = 215 KB/SM)

// ---------------- persistent device state ----------------
__device__ __align__(16) float d_h0[BT * HH];
__device__ __align__(16) float d_h1[BT * HH];
__device__ __align__(16) __nv_bfloat16 d_h0hi[BT * HH];
__device__ __align__(16) __nv_bfloat16 d_h0lo[BT * HH];
__device__ __align__(16) __nv_bfloat16 d_h1hi[BT * HH];
__device__ __align__(16) __nv_bfloat16 d_h1lo[BT * HH];
__device__ __align__(16) float d_GA[BT * NG];
__device__ __align__(16) float d_PB0[BT * NG];
__device__ __align__(16) float d_PB1[BT * NG];
__device__ unsigned d_barCount;
__device__ volatile unsigned d_barGen;

__global__ void gru_init()
{
    int i  = blockIdx.x * blockDim.x + threadIdx.x;
    int st = gridDim.x * blockDim.x;
    for (int e = i; e < BT * HH; e += st) { d_h0[e] = 0.f; d_h1[e] = 0.f; }
    unsigned* z0 = (unsigned*)d_h0hi; unsigned* z1 = (unsigned*)d_h0lo;
    unsigned* z2 = (unsigned*)d_h1hi; unsigned* z3 = (unsigned*)d_h1lo;
    for (int e = i; e < (BT * HH) / 2; e += st) { z0[e] = 0u; z1[e] = 0u; z2[e] = 0u; z3[e] = 0u; }
    for (int e = i; e < BT * NG; e += st) d_GA[e] = 0.f;
    if (i == 0) { d_barCount = 0u; d_barGen = 0u; }
}

// ---------------- software grid barrier (all NCTA CTAs resident) ----------------
__device__ __forceinline__ void gridBarrier()
{
    __syncthreads();
    if (threadIdx.x == 0) {
        __threadfence();
        unsigned gen = d_barGen;
        if (atomicAdd(&d_barCount, 1u) == (unsigned)gridDim.x - 1u) {
            d_barCount = 0u;
            __threadfence();
            d_barGen = gen + 1u;
        } else {
            while (d_barGen == gen) __nanosleep(64);
        }
        __threadfence();
    }
    __syncthreads();
}

// ---------------- cp.async + misc PTX ----------------
__device__ __forceinline__ unsigned s2u(const void* p)
{
    unsigned a;
    asm("{ .reg .u64 t; cvta.to.shared.u64 t, %1; cvt.u32.u64 %0, t; }" : "=r"(a) : "l"(p));
    return a;
}
#define CPA16(d, s)  asm volatile("cp.async.cg.shared.global [%0], [%1], 16;" :: "r"(d), "l"(s) : "memory")
#define CP_COMMIT()  asm volatile("cp.async.commit_group;" ::: "memory")
#define CP_WAIT1()   asm volatile("cp.async.wait_group 1;" ::: "memory")
#define CP_WAIT0()   asm volatile("cp.async.wait_group 0;" ::: "memory")

// mma.sync m16n8k16 row.col bf16 -> f32
#define MMA16816(C, A, b0, b1)                                                  \
    asm volatile("mma.sync.aligned.m16n8k16.row.col.f32.bf16.bf16.f32 "         \
                 "{%0,%1,%2,%3},{%4,%5,%6,%7},{%8,%9},{%0,%1,%2,%3};"           \
                 : "+f"((C)[0]), "+f"((C)[1]), "+f"((C)[2]), "+f"((C)[3])       \
                 : "r"((A)[0]), "r"((A)[1]), "r"((A)[2]), "r"((A)[3]),          \
                   "r"(b0), "r"(b1))

// ---------------- bf16 split helpers ----------------
__device__ __forceinline__ unsigned pack_bf2(float a, float b)
{
    __nv_bfloat162 t = __floats2bfloat162_rn(a, b);   // .x = a (low half)
    return *reinterpret_cast<unsigned*>(&t);
}
__device__ __forceinline__ float bflo(float v)
{
    return v - __bfloat162float(__float2bfloat16_rn(v));
}

// ---------------- one-time weight slice (32 x 512) -> smem (bf16 hi/lo) ----------------
__device__ void preloadW(const float* __restrict__ Wsl, char* smem)
{
    __nv_bfloat16* Whi = (__nv_bfloat16*)(smem + W_OFF);
    __nv_bfloat16* Wlo = (__nv_bfloat16*)(smem + W_OFF + SMEM_W);
    for (int idx = threadIdx.x; idx < 32 * (HH / 4); idx += NTHR) {
        int n  = idx >> 7;             // 0..31
        int k4 = (idx & 127) << 2;     // 0..508
        float4 w = *(const float4*)(Wsl + n * HH + k4);
        uint2 hv, lv;
        hv.x = pack_bf2(w.x, w.y);             hv.y = pack_bf2(w.z, w.w);
        lv.x = pack_bf2(bflo(w.x), bflo(w.y)); lv.y = pack_bf2(bflo(w.z), bflo(w.w));
        *(uint2*)(Whi + n * WST + k4) = hv;
        *(uint2*)(Wlo + n * WST + k4) = lv;
    }
}

// ---------------- cp.async stage of one 32-k A chunk (hi+lo) ----------------
__device__ __forceinline__ void issueChunk(const __nv_bfloat16* __restrict__ Ahi,
                                           const __nv_bfloat16* __restrict__ Alo,
                                           unsigned smem_u, int stage, int m0, int c)
{
    int t = threadIdx.x;
    int row = t >> 1, half = t & 1;
    const char* gh = (const char*)(Ahi + (m0 + row) * HH + c * 32 + half * 16);
    const char* gl = (const char*)(Alo + (m0 + row) * HH + c * 32 + half * 16);
    unsigned bh = smem_u + A_OFF + (stage * 2 + 0) * ABUF + row * (AST * 2) + half * 32;
    unsigned bl = smem_u + A_OFF + (stage * 2 + 1) * ABUF + row * (AST * 2) + half * 32;
    CPA16(bh, gh);      CPA16(bh + 16, gh + 16);
    CPA16(bl, gl);      CPA16(bl + 16, gl + 16);
}

// ---------------- per-step 128x32xK512 tile gemm (split bf16, fp32 accum) ----------------
__device__ void tileStep(const __nv_bfloat16* __restrict__ Agh,
                         const __nv_bfloat16* __restrict__ Agl,
                         float* __restrict__ Cg, int m0, int n0,
                         char* smem, unsigned smem_u)
{
    const __nv_bfloat16* Whi = (const __nv_bfloat16*)(smem + W_OFF);
    const __nv_bfloat16* Wlo = (const __nv_bfloat16*)(smem + W_OFF + SMEM_W);

    const int tid  = threadIdx.x;
    const int wid  = tid >> 5;
    const int lane = tid & 31;
    const int g    = lane >> 2;        // 0..7
    const int t4   = lane & 3;         // 0..3
    const int wm   = wid & 1;          // m half (64 rows)
    const int wn   = wid >> 1;         // n eighth (8 cols), 0..3

    int aoff[4];
#pragma unroll
    for (int ma = 0; ma < 4; ++ma)
        aoff[ma] = (wm * 64 + ma * 16 + g) * AST + 2 * t4;
    const int boff = (wn * 8 + g) * WST + 2 * t4;

    float acc[4][4];
#pragma unroll
    for (int ma = 0; ma < 4; ++ma)
#pragma unroll
        for (int q = 0; q < 4; ++q) acc[ma][q] = 0.f;

    // prologue: fill both stages (prior step's reads fenced by grid barrier)
#pragma unroll
    for (int s = 0; s < NSTAGE; ++s) {
        issueChunk(Agh, Agl, smem_u, s, m0, s);
        CP_COMMIT();
    }

#pragma unroll 1
    for (int c = 0; c < 16; ++c) {
        int stg = c & 1;
        CP_WAIT1();                // chunk c's group complete
        __syncthreads();

        const __nv_bfloat16* Ah = (const __nv_bfloat16*)(smem + A_OFF + (stg * 2 + 0) * ABUF);
        const __nv_bfloat16* Al = (const __nv_bfloat16*)(smem + A_OFF + (stg * 2 + 1) * ABUF);
#pragma unroll
        for (int ks = 0; ks < 32; ks += 16) {
            unsigned ah[4][4], al[4][4];
#pragma unroll
            for (int ma = 0; ma < 4; ++ma) {
                int o = aoff[ma] + ks;
                ah[ma][0] = *(const unsigned*)(Ah + o);
                ah[ma][1] = *(const unsigned*)(Ah + o + 8 * AST);
                ah[ma][2] = *(const unsigned*)(Ah + o + 8);
                ah[ma][3] = *(const unsigned*)(Ah + o + 8 * AST + 8);
                al[ma][0] = *(const unsigned*)(Al + o);
                al[ma][1] = *(const unsigned*)(Al + o + 8 * AST);
                al[ma][2] = *(const unsigned*)(Al + o + 8);
                al[ma][3] = *(const unsigned*)(Al + o + 8 * AST + 8);
            }
            int ob = boff + c * 32 + ks;
            unsigned bh0 = *(const unsigned*)(Whi + ob);
            unsigned bh1 = *(const unsigned*)(Whi + ob + 8);
            unsigned bl0 = *(const unsigned*)(Wlo + ob);
            unsigned bl1 = *(const unsigned*)(Wlo + ob + 8);
#pragma unroll
            for (int ma = 0; ma < 4; ++ma) {
                MMA16816(acc[ma], ah[ma], bh0, bh1);   // hi*hi
                MMA16816(acc[ma], ah[ma], bl0, bl1);   // hi*lo
                MMA16816(acc[ma], al[ma], bh0, bh1);   // lo*hi
            }
        }

        __syncthreads();           // all warps done reading stage stg (WAR)
        if (c + NSTAGE < 16)
            issueChunk(Agh, Agl, smem_u, stg, m0, c + NSTAGE);
        CP_COMMIT();               // commit (possibly empty) to keep group count
    }
    CP_WAIT0();

    // epilogue: per-lane fragment layout of C (m16n8)
#pragma unroll
    for (int ma = 0; ma < 4; ++ma) {
        int row = m0 + wm * 64 + ma * 16 + g;
        int col = n0 + wn * 8 + 2 * t4;
        float2 v0; v0.x = acc[ma][0]; v0.y = acc[ma][1];
        float2 v1; v1.x = acc[ma][2]; v1.y = acc[ma][3];
        *(float2*)(Cg + row * NG + col)       = v0;
        *(float2*)(Cg + (row + 8) * NG + col) = v1;
    }
}

// ---------------- activations (exact; also emit bf16 hi/lo of h) ----------------
__device__ __forceinline__ float sigmoidf_(float v) { return 1.f / (1.f + expf(-v)); }

__device__ void actA(const float* __restrict__ x, const float* __restrict__ Wi0,
                     const float* __restrict__ bi0, const float* __restrict__ bh, int t)
{
    int gtid = blockIdx.x * blockDim.x + threadIdx.x;
    int st   = gridDim.x * blockDim.x;
    for (int idx = gtid; idx < (BT * HH) / 4; idx += st) {
        int b = idx >> 7;
        int n = (idx & 127) << 2;
        float xv = x[b * TT + t];
        const float* G = d_GA + b * NG + n;
        float4 g0 = *(const float4*)(G);
        float4 g1 = *(const float4*)(G + HH);
        float4 g2 = *(const float4*)(G + 2 * HH);
        float4 w0 = *(const float4*)(Wi0 + n);
        float4 w1 = *(const float4*)(Wi0 + HH + n);
        float4 w2 = *(const float4*)(Wi0 + 2 * HH + n);
        float4 c0 = *(const float4*)(bi0 + n);
        float4 c1 = *(const float4*)(bi0 + HH + n);
        float4 c2 = *(const float4*)(bi0 + 2 * HH + n);
        float4 d0 = *(const float4*)(bh + n);
        float4 d1 = *(const float4*)(bh + HH + n);
        float4 d2 = *(const float4*)(bh + 2 * HH + n);
        float4 ho = *(const float4*)(d_h0 + b * HH + n);
        float4 res;
        const float* pg0 = (const float*)&g0; const float* pg1 = (const float*)&g1;
        const float* pg2 = (const float*)&g2;
        const float* pw0 = (const float*)&w0; const float* pw1 = (const float*)&w1;
        const float* pw2 = (const float*)&w2;
        const float* pc0 = (const float*)&c0; const float* pc1 = (const float*)&c1;
        const float* pc2 = (const float*)&c2;
        const float* pd0 = (const float*)&d0; const float* pd1 = (const float*)&d1;
        const float* pd2 = (const float*)&d2;
        const float* pho = (const float*)&ho;
        float* pr = (float*)&res;
#pragma unroll
        for (int l = 0; l < 4; ++l) {
            float r  = sigmoidf_(pg0[l] + pd0[l] + xv * pw0[l] + pc0[l]);
            float z  = sigmoidf_(pg1[l] + pd1[l] + xv * pw1[l] + pc1[l]);
            float nn = tanhf(xv * pw2[l] + pc2[l] + r * (pg2[l] + pd2[l]));
            pr[l] = (1.f - z) * nn + z * pho[l];
        }
        *(float4*)(d_h0 + b * HH + n) = res;
        uint2 hv, lv;
        hv.x = pack_bf2(res.x, res.y);             hv.y = pack_bf2(res.z, res.w);
        lv.x = pack_bf2(bflo(res.x), bflo(res.y)); lv.y = pack_bf2(bflo(res.z), bflo(res.w));
        *(uint2*)(d_h0hi + b * HH + n) = hv;
        *(uint2*)(d_h0lo + b * HH + n) = lv;
    }
}

__device__ void actB(const float* __restrict__ bi1, const float* __restrict__ bh)
{
    int gtid = blockIdx.x * blockDim.x + threadIdx.x;
    int st   = gridDim.x * blockDim.x;
    for (int idx = gtid; idx < (BT * HH) / 4; idx += st) {
        int b = idx >> 7;
        int n = (idx & 127) << 2;
        const float* P0 = d_PB0 + b * NG + n;
        const float* P1 = d_PB1 + b * NG + n;
        float4 i0 = *(const float4*)(P0);
        float4 i1 = *(const float4*)(P0 + HH);
        float4 i2 = *(const float4*)(P0 + 2 * HH);
        float4 h0g = *(const float4*)(P1);
        float4 h1g = *(const float4*)(P1 + HH);
        float4 h2g = *(const float4*)(P1 + 2 * HH);
        float4 c0 = *(const float4*)(bi1 + n);
        float4 c1 = *(const float4*)(bi1 + HH + n);
        float4 c2 = *(const float4*)(bi1 + 2 * HH + n);
        float4 d0 = *(const float4*)(bh + NG + n);
        float4 d1 = *(const float4*)(bh + NG + HH + n);
        float4 d2 = *(const float4*)(bh + NG + 2 * HH + n);
        float4 ho = *(const float4*)(d_h1 + b * HH + n);
        float4 res;
        const float* pi0 = (const float*)&i0; const float* pi1 = (const float*)&i1;
        const float* pi2 = (const float*)&i2;
        const float* ph0 = (const float*)&h0g; const float* ph1 = (const float*)&h1g;
        const float* ph2 = (const float*)&h2g;
        const float* pc0 = (const float*)&c0; const float* pc1 = (const float*)&c1;
        const float* pc2 = (const float*)&c2;
        const float* pd0 = (const float*)&d0; const float* pd1 = (const float*)&d1;
        const float* pd2 = (const float*)&d2;
        const float* pho = (const float*)&ho;
        float* pr = (float*)&res;
#pragma unroll
        for (int l = 0; l < 4; ++l) {
            float r  = sigmoidf_(pi0[l] + pc0[l] + ph0[l] + pd0[l]);
            float z  = sigmoidf_(pi1[l] + pc1[l] + ph1[l] + pd1[l]);
            float nn = tanhf(pi2[l] + pc2[l] + r * (ph2[l] + pd2[l]));
            pr[l] = (1.f - z) * nn + z * pho[l];
        }
        *(float4*)(d_h1 + b * HH + n) = res;
        uint2 hv, lv;
        hv.x = pack_bf2(res.x, res.y);             hv.y = pack_bf2(res.z, res.w);
        lv.x = pack_bf2(bflo(res.x), bflo(res.y)); lv.y = pack_bf2(bflo(res.z), bflo(res.w));
        *(uint2*)(d_h1hi + b * HH + n) = hv;
        *(uint2*)(d_h1lo + b * HH + n) = lv;
    }
}

// ---------------- final FC ----------------
__device__ void fcOut(const float* __restrict__ fcw, const float* __restrict__ fcb,
                      float* __restrict__ out)
{
    __shared__ float red[2][8];
    if (blockIdx.x >= 128) return;
    for (int s = 0; s < 2; ++s) {
        int b = blockIdx.x * 2 + s;
        float p0 = 0.f, p1 = 0.f;
        for (int k = threadIdx.x; k < HH; k += NTHR) {
            float h = d_h1[b * HH + k];
            p0 += h * fcw[k];
            p1 += h * fcw[HH + k];
        }
#pragma unroll
        for (int o = 16; o; o >>= 1) {
            p0 += __shfl_down_sync(0xffffffffu, p0, o);
            p1 += __shfl_down_sync(0xffffffffu, p1, o);
        }
        int w = threadIdx.x >> 5;
        if ((threadIdx.x & 31) == 0) { red[0][w] = p0; red[1][w] = p1; }
        __syncthreads();
        if (threadIdx.x == 0) {
            float a0 = 0.f, a1 = 0.f;
#pragma unroll
            for (int ww = 0; ww < 8; ++ww) { a0 += red[0][ww]; a1 += red[1][ww]; }
            out[b * 2 + 0] = a0 + fcb[0];
            out[b * 2 + 1] = a1 + fcb[1];
        }
        __syncthreads();
    }
}

// ---------------- persistent kernel ----------------
__global__ void __launch_bounds__(NTHR, 2)
gru_persistent(const float* __restrict__ x,   const float* __restrict__ Wi0,
               const float* __restrict__ bi0, const float* __restrict__ Wi1,
               const float* __restrict__ bi1, const float* __restrict__ Wh,
               const float* __restrict__ bh,  const float* __restrict__ fcw,
               const float* __restrict__ fcb, float* __restrict__ out)
{
    extern __shared__ char smem[];
    const unsigned smem_u = s2u(smem);

    // fixed tile assignment: 3 gemms x 2 m-halves x 48 n-slots (32 wide)
    const int u = blockIdx.x;
    const int gsel = u / 96;           // 0: gi1, 1: gh1, 2: layer0-next
    const int tb   = u % 96;
    const int m0   = (tb / 48) * 128;
    const int n0   = (tb % 48) * 32;

    const __nv_bfloat16* Agh = (gsel == 1) ? d_h1hi : d_h0hi;
    const __nv_bfloat16* Agl = (gsel == 1) ? d_h1lo : d_h0lo;
    float* Cg = (gsel == 0) ? d_PB0 : ((gsel == 1) ? d_PB1 : d_GA);

    {
        const float* Wsl = (gsel == 0) ? (Wi1 + n0 * HH)
                         : (gsel == 1) ? (Wh + NG * HH + n0 * HH)
                                       : (Wh + n0 * HH);
        preloadW(Wsl, smem);
    }
    __syncthreads();

    actA(x, Wi0, bi0, bh, 0);          // h0(0); GA/h zeroed by init
    gridBarrier();

    for (int t = 0; t < TT - 1; ++t) {
        tileStep(Agh, Agl, Cg, m0, n0, smem, smem_u);
        gridBarrier();
        actB(bi1, bh);                 // h1(t)
        actA(x, Wi0, bi0, bh, t + 1);  // h0(t+1)
        gridBarrier();
    }

    if (u < 192) tileStep(Agh, Agl, Cg, m0, n0, smem, smem_u);   // last step
    gridBarrier();
    actB(bi1, bh);
    gridBarrier();

    fcOut(fcw, fcb, out);
}

// ---------------- launch ----------------
extern "C" void kernel_launch(void* const* d_in, const int* in_sizes, int n_in,
                              void* d_out, int out_size)
{
    (void)in_sizes; (void)n_in; (void)out_size;
    const float* x   = (const float*)d_in[0];
    const float* Wi0 = (const float*)d_in[1];
    const float* bi0 = (const float*)d_in[2];
    const float* Wi1 = (const float*)d_in[3];
    const float* bi1 = (const float*)d_in[4];
    const float* Wh  = (const float*)d_in[5];
    const float* bh  = (const float*)d_in[6];
    const float* fcw = (const float*)d_in[7];
    const float* fcb = (const float*)d_in[8];
    float* out = (float*)d_out;

    cudaFuncSetAttribute(gru_persistent,
                         cudaFuncAttributeMaxDynamicSharedMemorySize, SMEM_BYTES);

    gru_init<<<64, 256>>>();
    gru_persistent<<<NCTA, NTHR, SMEM_BYTES>>>(x, Wi0, bi0, Wi1, bi1, Wh, bh,
                                               fcw, fcb, out);
}

// round 14
// speedup vs baseline: 1.2774x; 1.2774x over previous
#include <cuda_runtime.h>
#include <cuda_bf16.h>
#include <math.h>

// GRU: B=256, T=512, H=512, L=2, O=2.
// Persistent kernel; bf16 hi/lo split GEMM on mma.sync.m16n8k16 (fp32 accum).
// Round-11 structure (148 CTAs, 128x64 tiles, pinned W) plus:
//   - RACE-FREE hierarchical grid barrier (monotonic counters, no resets)
//   - 64-wide k-chunks (8 chunks, 2-stage cp.async pipeline)

#define BT 256
#define TT 512
#define HH 512
#define NG 1536
#define NCTA 148
#define NTHR 256

#define WST 520                        // W smem row stride (bf16 elems)
#define AST 72                         // A smem row stride (bf16 elems, 64 + 8 pad)
#define SMEM_W (64 * WST * 2)          // 66,560 B per W array (hi or lo)
#define ABUF   (128 * AST * 2)         // 18,432 B per (stage, hi/lo)
#define W_OFF  0
#define A_OFF  (2 * SMEM_W)            // 133,120
#define NSTAGE 2
#define NCHUNK 8                       // 8 chunks x 64 k
#define SMEM_BYTES (A_OFF + NSTAGE * 2 * ABUF)   // 206,848 B

// ---------------- persistent device state ----------------
__device__ __align__(16) float d_h0[BT * HH];
__device__ __align__(16) float d_h1[BT * HH];
__device__ __align__(16) __nv_bfloat16 d_h0hi[BT * HH];
__device__ __align__(16) __nv_bfloat16 d_h0lo[BT * HH];
__device__ __align__(16) __nv_bfloat16 d_h1hi[BT * HH];
__device__ __align__(16) __nv_bfloat16 d_h1lo[BT * HH];
__device__ __align__(16) float d_GA[BT * NG];
__device__ __align__(16) float d_PB0[BT * NG];
__device__ __align__(16) float d_PB1[BT * NG];
// hierarchical barrier: MONOTONIC counters (never reset inside the kernel;
// re-zeroed by gru_init each launch). 16 group counters on separate 128B lines.
__device__ unsigned d_grpCount[16 * 32];
__device__ unsigned d_rootCount;
__device__ volatile unsigned d_barGen;

__global__ void gru_init()
{
    int i  = blockIdx.x * blockDim.x + threadIdx.x;
    int st = gridDim.x * blockDim.x;
    for (int e = i; e < BT * HH; e += st) { d_h0[e] = 0.f; d_h1[e] = 0.f; }
    unsigned* z0 = (unsigned*)d_h0hi; unsigned* z1 = (unsigned*)d_h0lo;
    unsigned* z2 = (unsigned*)d_h1hi; unsigned* z3 = (unsigned*)d_h1lo;
    for (int e = i; e < (BT * HH) / 2; e += st) { z0[e] = 0u; z1[e] = 0u; z2[e] = 0u; z3[e] = 0u; }
    for (int e = i; e < BT * NG; e += st) d_GA[e] = 0.f;
    if (i < 16 * 32) d_grpCount[i] = 0u;
    if (i == 0) { d_rootCount = 0u; d_barGen = 0u; }
}

// ---------------- race-free hierarchical grid barrier ----------------
// A CTA entering this barrier has d_barGen == gen exactly (it cannot run ahead,
// and gen cannot advance without its arrival). Group g's counter reaches
// (gen+1)*gsz exactly when all its members arrive at generation gen; the last
// one arrives at the root. No counter is ever reset -> no store/atomic race.
__device__ __forceinline__ void gridBarrier()
{
    __syncthreads();
    if (threadIdx.x == 0) {
        __threadfence();
        unsigned gen = d_barGen;
        unsigned grp = blockIdx.x & 15u;
        unsigned gsz = (grp < (NCTA & 15u)) ? (NCTA / 16 + 1) : (NCTA / 16);
        unsigned arrived = atomicAdd(&d_grpCount[grp * 32], 1u) + 1u;
        if (arrived == (gen + 1u) * gsz) {
            unsigned rootArr = atomicAdd(&d_rootCount, 1u) + 1u;
            if (rootArr == (gen + 1u) * 16u) {
                __threadfence();
                d_barGen = gen + 1u;
            }
        }
        while (d_barGen == gen) __nanosleep(32);
        __threadfence();
    }
    __syncthreads();
}

// ---------------- cp.async + misc PTX ----------------
__device__ __forceinline__ unsigned s2u(const void* p)
{
    unsigned a;
    asm("{ .reg .u64 t; cvta.to.shared.u64 t, %1; cvt.u32.u64 %0, t; }" : "=r"(a) : "l"(p));
    return a;
}
#define CPA16(d, s)  asm volatile("cp.async.cg.shared.global [%0], [%1], 16;" :: "r"(d), "l"(s) : "memory")
#define CP_COMMIT()  asm volatile("cp.async.commit_group;" ::: "memory")
#define CP_WAIT1()   asm volatile("cp.async.wait_group 1;" ::: "memory")
#define CP_WAIT0()   asm volatile("cp.async.wait_group 0;" ::: "memory")

// mma.sync m16n8k16 row.col bf16 -> f32
#define MMA16816(C, A, b0, b1)                                                  \
    asm volatile("mma.sync.aligned.m16n8k16.row.col.f32.bf16.bf16.f32 "         \
                 "{%0,%1,%2,%3},{%4,%5,%6,%7},{%8,%9},{%0,%1,%2,%3};"           \
                 : "+f"((C)[0]), "+f"((C)[1]), "+f"((C)[2]), "+f"((C)[3])       \
                 : "r"((A)[0]), "r"((A)[1]), "r"((A)[2]), "r"((A)[3]),          \
                   "r"(b0), "r"(b1))

// ---------------- bf16 split helpers ----------------
__device__ __forceinline__ unsigned pack_bf2(float a, float b)
{
    __nv_bfloat162 t = __floats2bfloat162_rn(a, b);   // .x = a (low half)
    return *reinterpret_cast<unsigned*>(&t);
}
__device__ __forceinline__ float bflo(float v)
{
    return v - __bfloat162float(__float2bfloat16_rn(v));
}

// ---------------- one-time weight slice -> smem (bf16 hi/lo) ----------------
__device__ void preloadW(const float* __restrict__ Wsl, char* smem)
{
    __nv_bfloat16* Whi = (__nv_bfloat16*)(smem + W_OFF);
    __nv_bfloat16* Wlo = (__nv_bfloat16*)(smem + W_OFF + SMEM_W);
    for (int idx = threadIdx.x; idx < 64 * (HH / 4); idx += NTHR) {
        int n  = idx >> 7;             // 0..63
        int k4 = (idx & 127) << 2;     // 0..508
        float4 w = *(const float4*)(Wsl + n * HH + k4);
        uint2 hv, lv;
        hv.x = pack_bf2(w.x, w.y);             hv.y = pack_bf2(w.z, w.w);
        lv.x = pack_bf2(bflo(w.x), bflo(w.y)); lv.y = pack_bf2(bflo(w.z), bflo(w.w));
        *(uint2*)(Whi + n * WST + k4) = hv;
        *(uint2*)(Wlo + n * WST + k4) = lv;
    }
}

// ---------------- cp.async stage of one 64-k A chunk (hi+lo) ----------------
// thread t: row = t>>1 (0..127), half = t&1 (32 elems = 64B each), 4x CPA16 per array.
__device__ __forceinline__ void issueChunk(const __nv_bfloat16* __restrict__ Ahi,
                                           const __nv_bfloat16* __restrict__ Alo,
                                           unsigned smem_u, int stage, int m0, int c)
{
    int t = threadIdx.x;
    int row = t >> 1, half = t & 1;
    const char* gh = (const char*)(Ahi + (m0 + row) * HH + c * 64 + half * 32);
    const char* gl = (const char*)(Alo + (m0 + row) * HH + c * 64 + half * 32);
    unsigned bh = smem_u + A_OFF + (stage * 2 + 0) * ABUF + row * (AST * 2) + half * 64;
    unsigned bl = smem_u + A_OFF + (stage * 2 + 1) * ABUF + row * (AST * 2) + half * 64;
    CPA16(bh, gh);           CPA16(bh + 16, gh + 16);
    CPA16(bh + 32, gh + 32); CPA16(bh + 48, gh + 48);
    CPA16(bl, gl);           CPA16(bl + 16, gl + 16);
    CPA16(bl + 32, gl + 32); CPA16(bl + 48, gl + 48);
}

// ---------------- per-step 128x64xK512 tile gemm (split bf16, fp32 accum) ----------------
__device__ void tileStep(const __nv_bfloat16* __restrict__ Agh,
                         const __nv_bfloat16* __restrict__ Agl,
                         float* __restrict__ Cg, int m0, int n0,
                         char* smem, unsigned smem_u)
{
    const __nv_bfloat16* Whi = (const __nv_bfloat16*)(smem + W_OFF);
    const __nv_bfloat16* Wlo = (const __nv_bfloat16*)(smem + W_OFF + SMEM_W);

    const int tid  = threadIdx.x;
    const int wid  = tid >> 5;
    const int lane = tid & 31;
    const int g    = lane >> 2;        // 0..7
    const int t4   = lane & 3;         // 0..3
    const int wm   = wid & 1;          // m half (64)
    const int wn   = wid >> 1;         // n quarter (16)

    int aoff[4];
#pragma unroll
    for (int ma = 0; ma < 4; ++ma)
        aoff[ma] = (wm * 64 + ma * 16 + g) * AST + 2 * t4;
    int boff[2];
#pragma unroll
    for (int na = 0; na < 2; ++na)
        boff[na] = (wn * 16 + na * 8 + g) * WST + 2 * t4;

    float acc[4][2][4];
#pragma unroll
    for (int ma = 0; ma < 4; ++ma)
#pragma unroll
        for (int na = 0; na < 2; ++na)
#pragma unroll
            for (int q = 0; q < 4; ++q) acc[ma][na][q] = 0.f;

    // prologue: fill both stages (prior step's reads fenced by grid barrier)
#pragma unroll
    for (int s = 0; s < NSTAGE; ++s) {
        issueChunk(Agh, Agl, smem_u, s, m0, s);
        CP_COMMIT();
    }

#pragma unroll 1
    for (int c = 0; c < NCHUNK; ++c) {
        int stg = c & 1;
        CP_WAIT1();                // chunk c's group complete
        __syncthreads();

        const __nv_bfloat16* Ah = (const __nv_bfloat16*)(smem + A_OFF + (stg * 2 + 0) * ABUF);
        const __nv_bfloat16* Al = (const __nv_bfloat16*)(smem + A_OFF + (stg * 2 + 1) * ABUF);
#pragma unroll
        for (int ks = 0; ks < 64; ks += 16) {
            unsigned ah[4][4], al[4][4];
#pragma unroll
            for (int ma = 0; ma < 4; ++ma) {
                int o = aoff[ma] + ks;
                ah[ma][0] = *(const unsigned*)(Ah + o);
                ah[ma][1] = *(const unsigned*)(Ah + o + 8 * AST);
                ah[ma][2] = *(const unsigned*)(Ah + o + 8);
                ah[ma][3] = *(const unsigned*)(Ah + o + 8 * AST + 8);
                al[ma][0] = *(const unsigned*)(Al + o);
                al[ma][1] = *(const unsigned*)(Al + o + 8 * AST);
                al[ma][2] = *(const unsigned*)(Al + o + 8);
                al[ma][3] = *(const unsigned*)(Al + o + 8 * AST + 8);
            }
#pragma unroll
            for (int na = 0; na < 2; ++na) {
                int ob = boff[na] + c * 64 + ks;
                unsigned bh0 = *(const unsigned*)(Whi + ob);
                unsigned bh1 = *(const unsigned*)(Whi + ob + 8);
                unsigned bl0 = *(const unsigned*)(Wlo + ob);
                unsigned bl1 = *(const unsigned*)(Wlo + ob + 8);
#pragma unroll
                for (int ma = 0; ma < 4; ++ma) {
                    MMA16816(acc[ma][na], ah[ma], bh0, bh1);   // hi*hi
                    MMA16816(acc[ma][na], ah[ma], bl0, bl1);   // hi*lo
                    MMA16816(acc[ma][na], al[ma], bh0, bh1);   // lo*hi
                }
            }
        }

        __syncthreads();           // all warps done reading stage stg (WAR)
        if (c + NSTAGE < NCHUNK)
            issueChunk(Agh, Agl, smem_u, stg, m0, c + NSTAGE);
        CP_COMMIT();               // commit (possibly empty) to keep group count
    }
    CP_WAIT0();

    // epilogue: per-lane fragment layout of C (m16n8)
#pragma unroll
    for (int ma = 0; ma < 4; ++ma) {
        int row = m0 + wm * 64 + ma * 16 + g;
#pragma unroll
        for (int na = 0; na < 2; ++na) {
            int col = n0 + wn * 16 + na * 8 + 2 * t4;
            float2 v0; v0.x = acc[ma][na][0]; v0.y = acc[ma][na][1];
            float2 v1; v1.x = acc[ma][na][2]; v1.y = acc[ma][na][3];
            *(float2*)(Cg + row * NG + col)       = v0;
            *(float2*)(Cg + (row + 8) * NG + col) = v1;
        }
    }
}

// ---------------- activations (exact; also emit bf16 hi/lo of h) ----------------
__device__ __forceinline__ float sigmoidf_(float v) { return 1.f / (1.f + expf(-v)); }

__device__ void actA(const float* __restrict__ x, const float* __restrict__ Wi0,
                     const float* __restrict__ bi0, const float* __restrict__ bh, int t)
{
    int gtid = blockIdx.x * blockDim.x + threadIdx.x;
    int st   = gridDim.x * blockDim.x;
    for (int idx = gtid; idx < (BT * HH) / 4; idx += st) {
        int b = idx >> 7;
        int n = (idx & 127) << 2;
        float xv = x[b * TT + t];
        const float* G = d_GA + b * NG + n;
        float4 g0 = *(const float4*)(G);
        float4 g1 = *(const float4*)(G + HH);
        float4 g2 = *(const float4*)(G + 2 * HH);
        float4 w0 = *(const float4*)(Wi0 + n);
        float4 w1 = *(const float4*)(Wi0 + HH + n);
        float4 w2 = *(const float4*)(Wi0 + 2 * HH + n);
        float4 c0 = *(const float4*)(bi0 + n);
        float4 c1 = *(const float4*)(bi0 + HH + n);
        float4 c2 = *(const float4*)(bi0 + 2 * HH + n);
        float4 d0 = *(const float4*)(bh + n);
        float4 d1 = *(const float4*)(bh + HH + n);
        float4 d2 = *(const float4*)(bh + 2 * HH + n);
        float4 ho = *(const float4*)(d_h0 + b * HH + n);
        float4 res;
        const float* pg0 = (const float*)&g0; const float* pg1 = (const float*)&g1;
        const float* pg2 = (const float*)&g2;
        const float* pw0 = (const float*)&w0; const float* pw1 = (const float*)&w1;
        const float* pw2 = (const float*)&w2;
        const float* pc0 = (const float*)&c0; const float* pc1 = (const float*)&c1;
        const float* pc2 = (const float*)&c2;
        const float* pd0 = (const float*)&d0; const float* pd1 = (const float*)&d1;
        const float* pd2 = (const float*)&d2;
        const float* pho = (const float*)&ho;
        float* pr = (float*)&res;
#pragma unroll
        for (int l = 0; l < 4; ++l) {
            float r  = sigmoidf_(pg0[l] + pd0[l] + xv * pw0[l] + pc0[l]);
            float z  = sigmoidf_(pg1[l] + pd1[l] + xv * pw1[l] + pc1[l]);
            float nn = tanhf(xv * pw2[l] + pc2[l] + r * (pg2[l] + pd2[l]));
            pr[l] = (1.f - z) * nn + z * pho[l];
        }
        *(float4*)(d_h0 + b * HH + n) = res;
        uint2 hv, lv;
        hv.x = pack_bf2(res.x, res.y);             hv.y = pack_bf2(res.z, res.w);
        lv.x = pack_bf2(bflo(res.x), bflo(res.y)); lv.y = pack_bf2(bflo(res.z), bflo(res.w));
        *(uint2*)(d_h0hi + b * HH + n) = hv;
        *(uint2*)(d_h0lo + b * HH + n) = lv;
    }
}

__device__ void actB(const float* __restrict__ bi1, const float* __restrict__ bh)
{
    int gtid = blockIdx.x * blockDim.x + threadIdx.x;
    int st   = gridDim.x * blockDim.x;
    for (int idx = gtid; idx < (BT * HH) / 4; idx += st) {
        int b = idx >> 7;
        int n = (idx & 127) << 2;
        const float* P0 = d_PB0 + b * NG + n;
        const float* P1 = d_PB1 + b * NG + n;
        float4 i0 = *(const float4*)(P0);
        float4 i1 = *(const float4*)(P0 + HH);
        float4 i2 = *(const float4*)(P0 + 2 * HH);
        float4 h0g = *(const float4*)(P1);
        float4 h1g = *(const float4*)(P1 + HH);
        float4 h2g = *(const float4*)(P1 + 2 * HH);
        float4 c0 = *(const float4*)(bi1 + n);
        float4 c1 = *(const float4*)(bi1 + HH + n);
        float4 c2 = *(const float4*)(bi1 + 2 * HH + n);
        float4 d0 = *(const float4*)(bh + NG + n);
        float4 d1 = *(const float4*)(bh + NG + HH + n);
        float4 d2 = *(const float4*)(bh + NG + 2 * HH + n);
        float4 ho = *(const float4*)(d_h1 + b * HH + n);
        float4 res;
        const float* pi0 = (const float*)&i0; const float* pi1 = (const float*)&i1;
        const float* pi2 = (const float*)&i2;
        const float* ph0 = (const float*)&h0g; const float* ph1 = (const float*)&h1g;
        const float* ph2 = (const float*)&h2g;
        const float* pc0 = (const float*)&c0; const float* pc1 = (const float*)&c1;
        const float* pc2 = (const float*)&c2;
        const float* pd0 = (const float*)&d0; const float* pd1 = (const float*)&d1;
        const float* pd2 = (const float*)&d2;
        const float* pho = (const float*)&ho;
        float* pr = (float*)&res;
#pragma unroll
        for (int l = 0; l < 4; ++l) {
            float r  = sigmoidf_(pi0[l] + pc0[l] + ph0[l] + pd0[l]);
            float z  = sigmoidf_(pi1[l] + pc1[l] + ph1[l] + pd1[l]);
            float nn = tanhf(pi2[l] + pc2[l] + r * (ph2[l] + pd2[l]));
            pr[l] = (1.f - z) * nn + z * pho[l];
        }
        *(float4*)(d_h1 + b * HH + n) = res;
        uint2 hv, lv;
        hv.x = pack_bf2(res.x, res.y);             hv.y = pack_bf2(res.z, res.w);
        lv.x = pack_bf2(bflo(res.x), bflo(res.y)); lv.y = pack_bf2(bflo(res.z), bflo(res.w));
        *(uint2*)(d_h1hi + b * HH + n) = hv;
        *(uint2*)(d_h1lo + b * HH + n) = lv;
    }
}

// ---------------- final FC ----------------
__device__ void fcOut(const float* __restrict__ fcw, const float* __restrict__ fcb,
                      float* __restrict__ out)
{
    __shared__ float red[2][8];
    if (blockIdx.x >= 128) return;
    for (int s = 0; s < 2; ++s) {
        int b = blockIdx.x * 2 + s;
        float p0 = 0.f, p1 = 0.f;
        for (int k = threadIdx.x; k < HH; k += NTHR) {
            float h = d_h1[b * HH + k];
            p0 += h * fcw[k];
            p1 += h * fcw[HH + k];
        }
#pragma unroll
        for (int o = 16; o; o >>= 1) {
            p0 += __shfl_down_sync(0xffffffffu, p0, o);
            p1 += __shfl_down_sync(0xffffffffu, p1, o);
        }
        int w = threadIdx.x >> 5;
        if ((threadIdx.x & 31) == 0) { red[0][w] = p0; red[1][w] = p1; }
        __syncthreads();
        if (threadIdx.x == 0) {
            float a0 = 0.f, a1 = 0.f;
#pragma unroll
            for (int ww = 0; ww < 8; ++ww) { a0 += red[0][ww]; a1 += red[1][ww]; }
            out[b * 2 + 0] = a0 + fcb[0];
            out[b * 2 + 1] = a1 + fcb[1];
        }
        __syncthreads();
    }
}

// ---------------- persistent kernel ----------------
__global__ void __launch_bounds__(NTHR, 1)
gru_persistent(const float* __restrict__ x,   const float* __restrict__ Wi0,
               const float* __restrict__ bi0, const float* __restrict__ Wi1,
               const float* __restrict__ bi1, const float* __restrict__ Wh,
               const float* __restrict__ bh,  const float* __restrict__ fcw,
               const float* __restrict__ fcb, float* __restrict__ out)
{
    extern __shared__ char smem[];
    const unsigned smem_u = s2u(smem);

    // fixed tile assignment
    const int u = blockIdx.x;
    const bool active = (u < 144);
    const int gsel = u / 48;           // 0: gi1, 1: gh1, 2: layer0-next
    const int tb   = u % 48;
    const int m0   = (tb / 24) * 128;
    const int n0   = (tb % 24) * 64;

    const __nv_bfloat16* Agh = (gsel == 1) ? d_h1hi : d_h0hi;
    const __nv_bfloat16* Agl = (gsel == 1) ? d_h1lo : d_h0lo;
    float* Cg = (gsel == 0) ? d_PB0 : ((gsel == 1) ? d_PB1 : d_GA);

    if (active) {
        const float* Wsl = (gsel == 0) ? (Wi1 + n0 * HH)
                         : (gsel == 1) ? (Wh + NG * HH + n0 * HH)
                                       : (Wh + n0 * HH);
        preloadW(Wsl, smem);
    }
    __syncthreads();

    actA(x, Wi0, bi0, bh, 0);          // h0(0); GA/h zeroed by init
    gridBarrier();

    for (int t = 0; t < TT - 1; ++t) {
        if (active) tileStep(Agh, Agl, Cg, m0, n0, smem, smem_u);
        gridBarrier();
        actB(bi1, bh);                 // h1(t)
        actA(x, Wi0, bi0, bh, t + 1);  // h0(t+1)
        gridBarrier();
    }

    if (u < 96) tileStep(Agh, Agl, Cg, m0, n0, smem, smem_u);   // last step
    gridBarrier();
    actB(bi1, bh);
    gridBarrier();

    fcOut(fcw, fcb, out);
}

// ---------------- launch ----------------
extern "C" void kernel_launch(void* const* d_in, const int* in_sizes, int n_in,
                              void* d_out, int out_size)
{
    (void)in_sizes; (void)n_in; (void)out_size;
    const float* x   = (const float*)d_in[0];
    const float* Wi0 = (const float*)d_in[1];
    const float* bi0 = (const float*)d_in[2];
    const float* Wi1 = (const float*)d_in[3];
    const float* bi1 = (const float*)d_in[4];
    const float* Wh  = (const float*)d_in[5];
    const float* bh  = (const float*)d_in[6];
    const float* fcw = (const float*)d_in[7];
    const float* fcb = (const float*)d_in[8];
    float* out = (float*)d_out;

    cudaFuncSetAttribute(gru_persistent,
                         cudaFuncAttributeMaxDynamicSharedMemorySize, SMEM_BYTES);

    gru_init<<<64, 256>>>();
    gru_persistent<<<NCTA, NTHR, SMEM_BYTES>>>(x, Wi0, bi0, Wi1, bi1, Wh, bh,
                                               fcw, fcb, out);
}